// round 3
// baseline (speedup 1.0000x reference)
#include <cuda_runtime.h>
#include <cstdint>

#define Lq     8192
#define Eq     256
#define HDq    256
#define NCOL   2048      // 2 dirs * 4*HD
#define Tq     34
#define STARTq 32

// ---------------- scratch (static device globals; no runtime allocation) ----
__device__ float g_gates[Lq * NCOL];   // 64 MB: precomputed x@Wih^T + b, both dirs
__device__ float g_h[Lq * 512];        // 16 MB: [hf | hb]
__device__ float g_feats[Lq * Tq];
__device__ float g_la[Lq * Tq];
__device__ float g_lb[Lq * Tq];

// ============================================================================
// Phase A: embedding gather + input projection GEMM
// C[t][col] = sum_e embed[words[t]][e] * Wih[col][e] + b[col],  col in [0,2048)
// cols [0,1024) -> forward weights, [1024,2048) -> backward
// 64x64 tile, BK=32, 256 threads, 4x4 per thread
// ============================================================================
__global__ void xproj_kernel(const int* __restrict__ words,
                             const float* __restrict__ embed,
                             const float* __restrict__ Wf, const float* __restrict__ bf,
                             const float* __restrict__ Wb, const float* __restrict__ bb)
{
    __shared__ float As[32][64];
    __shared__ float Bs[32][64];
    __shared__ int   sw[64];

    const int tid = threadIdx.x;                 // 256 threads
    const int bn = blockIdx.x, bm = blockIdx.y;  // grid (32, 128)
    const int tx = tid & 15, ty = tid >> 4;      // 16x16

    if (tid < 64) sw[tid] = words[bm * 64 + tid];
    __syncthreads();

    float acc[4][4];
    #pragma unroll
    for (int i = 0; i < 4; i++)
        #pragma unroll
        for (int j = 0; j < 4; j++) acc[i][j] = 0.f;

    for (int k0 = 0; k0 < Eq; k0 += 32) {
        #pragma unroll
        for (int p = 0; p < 8; p++) {
            int lin = p * 256 + tid;
            int m = lin >> 5, kk = lin & 31;
            As[kk][m] = embed[(size_t)sw[m] * Eq + (k0 + kk)];
        }
        #pragma unroll
        for (int p = 0; p < 8; p++) {
            int lin = p * 256 + tid;
            int n = lin >> 5, kk = lin & 31;
            int col = bn * 64 + n;
            const float* W = (col < 1024) ? Wf : Wb;
            int row = (col < 1024) ? col : col - 1024;
            Bs[kk][n] = W[row * Eq + (k0 + kk)];
        }
        __syncthreads();
        #pragma unroll
        for (int kk = 0; kk < 32; kk++) {
            float4 av = *(const float4*)&As[kk][ty * 4];
            float4 bv = *(const float4*)&Bs[kk][tx * 4];
            float a[4] = {av.x, av.y, av.z, av.w};
            float b[4] = {bv.x, bv.y, bv.z, bv.w};
            #pragma unroll
            for (int i = 0; i < 4; i++)
                #pragma unroll
                for (int j = 0; j < 4; j++)
                    acc[i][j] = fmaf(a[i], b[j], acc[i][j]);
        }
        __syncthreads();
    }

    #pragma unroll
    for (int i = 0; i < 4; i++) {
        int t = bm * 64 + ty * 4 + i;
        #pragma unroll
        for (int j = 0; j < 4; j++) {
            int col = bn * 64 + tx * 4 + j;
            float bias = (col < 1024) ? bf[col] : bb[col - 1024];
            g_gates[(size_t)t * NCOL + col] = acc[i][j] + bias;
        }
    }
}

// ============================================================================
// Phase B: recurrent BiLSTM. Grid = 16 CTAs = 2 clusters of 8 (dir 0 fwd, 1 bwd)
// Each CTA: 512 threads, holds 128 gate-rows of Whh in registers (64 f32/thread)
//   warp w: gate g = w>>2, k-chunk kc = w&3 (64 wide); lane = row within slice.
// h (256) lives double-buffered in every CTA's SMEM; each CTA owns hidden units
// [rank*32, rank*32+32) and broadcasts them to all peers via DSMEM each step.
// ============================================================================
__device__ __forceinline__ void cluster_sync_all() {
    asm volatile("barrier.cluster.arrive.aligned;" ::: "memory");
    asm volatile("barrier.cluster.wait.aligned;" ::: "memory");
}

__global__ void __cluster_dims__(8, 1, 1) __launch_bounds__(512, 1)
lstm_kernel(const float* __restrict__ Whh_f, const float* __restrict__ Whh_b)
{
    __shared__ __align__(16) float sh_h[2][256];
    __shared__ float sh_part[16][32];
    __shared__ float sh_act[4][32];

    const int tid = threadIdx.x;
    unsigned rank;
    asm("mov.u32 %0, %%cluster_ctarank;" : "=r"(rank));
    const int dir  = blockIdx.x >> 3;
    const int w    = tid >> 5, lane = tid & 31;
    const int g    = w >> 2,   kc   = w & 3;
    const int row  = g * 256 + (int)rank * 32 + lane;
    const float* Whh = dir ? Whh_b : Whh_f;

    // load weights into registers: 64 floats = my row's k-chunk
    float wreg[64];
    {
        const float4* wp = (const float4*)(Whh + (size_t)row * 256 + kc * 64);
        #pragma unroll
        for (int q = 0; q < 16; q++) {
            float4 v = wp[q];
            wreg[4*q+0] = v.x; wreg[4*q+1] = v.y; wreg[4*q+2] = v.z; wreg[4*q+3] = v.w;
        }
    }

    if (tid < 256) { sh_h[0][tid] = 0.f; sh_h[1][tid] = 0.f; }
    __syncthreads();
    cluster_sync_all();   // all buffers zeroed cluster-wide before any DSMEM write

    float c = 0.f;                       // cell state (threads tid<32)
    const int g2 = tid >> 5;             // reducer role (tid<128): gate index
    const int l  = tid & 31;
    long  xbase = 0;
    float xpre  = 0.f;
    if (tid < 128) {
        int tp0 = dir ? (Lq - 1) : 0;
        xbase = (long)dir * 1024 + (long)g2 * 256 + (long)rank * 32 + l;
        xpre = g_gates[(long)tp0 * NCOL + xbase];
    }

    for (int it = 0; it < Lq; ++it) {
        const int tp  = dir ? (Lq - 1 - it) : it;
        const int buf = it & 1, nb = buf ^ 1;

        // prefetch next step's input-projection value (hides DRAM latency)
        float xnext = 0.f;
        if (tid < 128 && it + 1 < Lq) {
            int tpn = dir ? (Lq - 2 - it) : (it + 1);
            xnext = g_gates[(long)tpn * NCOL + xbase];
        }

        // recurrent matvec partial: 64 MACs against broadcast h
        const float4* hp = (const float4*)(&sh_h[buf][kc * 64]);
        float a0 = 0.f, a1 = 0.f, a2 = 0.f, a3 = 0.f;
        #pragma unroll
        for (int q = 0; q < 16; q++) {
            float4 hv = hp[q];
            a0 = fmaf(wreg[4*q+0], hv.x, a0);
            a1 = fmaf(wreg[4*q+1], hv.y, a1);
            a2 = fmaf(wreg[4*q+2], hv.z, a2);
            a3 = fmaf(wreg[4*q+3], hv.w, a3);
        }
        sh_part[w][lane] = (a0 + a1) + (a2 + a3);
        __syncthreads();

        if (tid < 128) {
            float gv = sh_part[g2*4+0][l] + sh_part[g2*4+1][l]
                     + sh_part[g2*4+2][l] + sh_part[g2*4+3][l] + xpre;
            gv = (g2 == 2) ? tanhf(gv) : (1.f / (1.f + __expf(-gv)));
            sh_act[g2][l] = gv;
        }
        xpre = xnext;
        __syncthreads();

        if (tid < 32) {
            float iv = sh_act[0][tid], fv = sh_act[1][tid];
            float gg = sh_act[2][tid], ov = sh_act[3][tid];
            c = fmaf(fv, c, iv * gg);
            float hv = ov * tanhf(c);
            // broadcast my h slice element to all 8 CTAs' next buffer
            unsigned off = ((unsigned)nb * 256u + rank * 32u + (unsigned)tid) * 4u;
            uint32_t sa = (uint32_t)__cvta_generic_to_shared(&sh_h[0][0]) + off;
            #pragma unroll
            for (int dst = 0; dst < 8; ++dst) {
                uint32_t pa;
                asm volatile("mapa.shared::cluster.u32 %0, %1, %2;"
                             : "=r"(pa) : "r"(sa), "r"(dst));
                asm volatile("st.shared::cluster.f32 [%0], %1;"
                             :: "r"(pa), "f"(hv) : "memory");
            }
            g_h[(long)tp * 512 + dir * 256 + (int)rank * 32 + tid] = hv;
        }
        cluster_sync_all();  // release DSMEM writes / acquire for next read
    }
}

// ============================================================================
// Phase C: feats[t][j] = h[t] . W_out[j] + b_out[j]   (K=512, T=34)
// block of 256 threads does 4 t-rows; h rows staged in SMEM (broadcast reads)
// ============================================================================
__global__ void feats_kernel(const float* __restrict__ Wout,
                             const float* __restrict__ bout)
{
    __shared__ float sh[4][512];
    const int tid = threadIdx.x;
    const int t0 = blockIdx.x * 4;
    #pragma unroll
    for (int p = 0; p < 8; p++) {
        int lin = p * 256 + tid;
        int r = lin >> 9, k = lin & 511;
        sh[r][k] = g_h[(long)(t0 + r) * 512 + k];
    }
    __syncthreads();
    const int tt = tid >> 6, j = tid & 63;
    if (j < Tq) {
        const float* wp = Wout + (size_t)j * 512;
        float s0 = 0.f, s1 = 0.f;
        #pragma unroll 8
        for (int k = 0; k < 512; k += 2) {
            s0 = fmaf(sh[tt][k],     __ldg(wp + k),     s0);
            s1 = fmaf(sh[tt][k + 1], __ldg(wp + k + 1), s1);
        }
        g_feats[(long)(t0 + tt) * Tq + j] = s0 + s1 + bout[j];
    }
}

// ============================================================================
// Phase D: CRF scans. block 0: forward alphas; block 1: backward betas.
// exp(trans) precomputed into registers; per step: center, exp, dot, log.
// ============================================================================
__global__ void crf_kernel(const float* __restrict__ trans)
{
    __shared__ float sa[64];
    __shared__ float se[64];
    const int j = threadIdx.x;   // 64 threads, j<34 active

    if (blockIdx.x == 0) {
        // ---------------- forward ----------------
        float er[Tq];
        if (j < Tq) {
            #pragma unroll
            for (int i = 0; i < Tq; i++) er[i] = __expf(trans[j * Tq + i]);
            sa[j] = (j == STARTq) ? 0.f : -10000.f;
        }
        __syncthreads();
        float feat = (j < Tq) ? __ldg(&g_feats[j]) : 0.f;

        for (int t = 0; t < Lq; t++) {
            float m = sa[0];
            #pragma unroll
            for (int i = 1; i < Tq; i++) m = fmaxf(m, sa[i]);
            if (j < Tq) se[j] = __expf(sa[j] - m);
            __syncthreads();
            float nv = 0.f;
            if (j < Tq) {
                float s0 = 0.f, s1 = 0.f;
                #pragma unroll
                for (int i = 0; i < Tq; i += 2) {
                    s0 = fmaf(er[i],     se[i],     s0);
                    s1 = fmaf(er[i + 1], se[i + 1], s1);
                }
                nv = feat + m + __logf(s0 + s1);
                g_la[(long)t * Tq + j] = nv;
            }
            feat = (j < Tq && t + 1 < Lq) ? __ldg(&g_feats[(long)(t + 1) * Tq + j]) : 0.f;
            __syncthreads();
            if (j < Tq) sa[j] = nv;
            __syncthreads();
        }
    } else {
        // ---------------- backward ----------------
        const int i = j;
        float ec[Tq];
        if (i < Tq) {
            float s = 0.f;
            #pragma unroll
            for (int jj = 0; jj < Tq; jj++) {
                ec[jj] = __expf(trans[jj * Tq + i]);   // column i
                s += ec[jj];
            }
            float bl = __logf(s);                      // lse_j trans[j][i]
            g_lb[(long)(Lq - 1) * Tq + i] = bl;
            sa[i] = bl;
        }
        __syncthreads();
        float featn = (i < Tq) ? __ldg(&g_feats[(long)(Lq - 1) * Tq + i]) : 0.f;

        for (int t = Lq - 2; t >= 0; t--) {
            if (i < Tq) se[i] = sa[i] + featn;         // v[j] = beta[j]+feat_{t+1}[j]
            __syncthreads();
            float m = se[0];
            #pragma unroll
            for (int jj = 1; jj < Tq; jj++) m = fmaxf(m, se[jj]);
            if (i < Tq) sa[i] = __expf(se[i] - m);     // reuse sa as exp(v - m)
            __syncthreads();
            float nb = 0.f;
            if (i < Tq) {
                float s0 = 0.f, s1 = 0.f;
                #pragma unroll
                for (int jj = 0; jj < Tq; jj += 2) {
                    s0 = fmaf(ec[jj],     sa[jj],     s0);
                    s1 = fmaf(ec[jj + 1], sa[jj + 1], s1);
                }
                nb = m + __logf(s0 + s1);
                g_lb[(long)t * Tq + i] = nb;
            }
            featn = (i < Tq && t > 0) ? __ldg(&g_feats[(long)t * Tq + i]) : 0.f;
            __syncthreads();
            if (i < Tq) sa[i] = nb;
            __syncthreads();
        }
    }
}

// ============================================================================
// Phase E: score = la + lb ; tags = argmax(score)  (first max wins)
// ============================================================================
__global__ void final_kernel(float* __restrict__ out, int out_size)
{
    int t = blockIdx.x * blockDim.x + threadIdx.x;
    if (t >= Lq) return;
    float best = -3.4e38f;
    int bi = 0;
    #pragma unroll
    for (int j = 0; j < Tq; j++) {
        float s = g_la[(long)t * Tq + j] + g_lb[(long)t * Tq + j];
        out[(long)t * Tq + j] = s;
        if (s > best) { best = s; bi = j; }
    }
    if (out_size >= Lq * Tq + Lq) out[(long)Lq * Tq + t] = (float)bi;
}

// ============================================================================
extern "C" void kernel_launch(void* const* d_in, const int* in_sizes, int n_in,
                              void* d_out, int out_size)
{
    const int*   words = (const int*)  d_in[0];
    const float* embed = (const float*)d_in[1];
    const float* Wih_f = (const float*)d_in[2];
    const float* Whh_f = (const float*)d_in[3];
    const float* b_f   = (const float*)d_in[4];
    const float* Wih_b = (const float*)d_in[5];
    const float* Whh_b = (const float*)d_in[6];
    const float* b_b   = (const float*)d_in[7];
    const float* W_out = (const float*)d_in[8];
    const float* b_out = (const float*)d_in[9];
    const float* trans = (const float*)d_in[10];
    float* out = (float*)d_out;

    xproj_kernel<<<dim3(32, 128), 256>>>(words, embed, Wih_f, b_f, Wih_b, b_b);
    lstm_kernel<<<16, 512>>>(Whh_f, Whh_b);
    feats_kernel<<<Lq / 4, 256>>>(W_out, b_out);
    crf_kernel<<<2, 64>>>(trans);
    final_kernel<<<(Lq + 127) / 128, 128>>>(out, out_size);
}